// round 15
// baseline (speedup 1.0000x reference)
#include <cuda_runtime.h>

// ---------------------------------------------------------------------------
// DummyGCN4: 4-layer GCN, output = h3[node 1] only.
// R15: R14's 5-step structure with CORRECTLY SIZED grids so the forked
// branch truly overlaps. All full-edge kernels use 391 blocks x 256 thr
// (8 edges/thread) — two such grids co-reside (782 <= GPU capacity), so
// branch B (zero agg0 + all-node layer-0 aggregation) runs CONCURRENTLY
// with scans 1-2 instead of serializing behind them (R11/R12/R14's flaw).
//   forked:  zagg0 -> agg0all                  (hidden under scans 1-2)
//   serial:  scan32 -> scan21 -> scan10+agg1(fused) -> h1x2 -> tail
// Scans are DRAM-latency-bound (~450GB/s each); concurrent pair ~900GB/s,
// far under HBM, so no mutual slowdown expected.
// ---------------------------------------------------------------------------

#define MAXN 50048
#define BMW  1568
#define OUT_NODE 1
#define E1CAP  16384      // edges with dst == OUT_NODE
#define E2CAP  65536      // edges with dst in B2

__device__ unsigned g_B1[BMW], g_B2[BMW];
__device__ int   g_list1[MAXN], g_list2[MAXN];
__device__ int   g_cnt1, g_cnt2;
__device__ int   g_e1s[E1CAP];                 __device__ int g_e1n;
__device__ int   g_e2s[E2CAP],  g_e2d[E2CAP];  __device__ int g_e2n;
__device__ float g_agg0[MAXN];
__device__ float g_agg1[(size_t)MAXN * 64];
__device__ float g_x2[(size_t)MAXN * 64];
__device__ float g_agg2[(size_t)MAXN * 64];
__device__ float g_x3[MAXN];

__device__ __forceinline__ float lrelu(float x) { return x >= 0.f ? x : 0.01f * x; }
__device__ __forceinline__ bool tb(const unsigned* b, int i) {
    return (b[i >> 5] >> (i & 31)) & 1u;
}
__device__ __forceinline__ void zero64(float* a) {
    float4 z = make_float4(0.f, 0.f, 0.f, 0.f);
    float4* a4 = (float4*)a;
    #pragma unroll
    for (int j = 0; j < 16; j++) a4[j] = z;
}

// ---------------- forked branch: zero agg0, then aggregate ALL edges --------
__global__ void k_zagg0() {
    int t = blockIdx.x * blockDim.x + threadIdx.x;
    if (t < MAXN) g_agg0[t] = 0.f;
}
__global__ void k_agg0all(const int* __restrict__ src, const int* __restrict__ dst,
                          const float* __restrict__ in_feat, int E) {
    int t = blockIdx.x * blockDim.x + threadIdx.x;
    int base = t * 8;
    if (base + 7 < E) {
        int4 d0 = __ldg((const int4*)(dst + base));
        int4 d1 = __ldg((const int4*)(dst + base + 4));
        int4 s0 = __ldg((const int4*)(src + base));
        int4 s1 = __ldg((const int4*)(src + base + 4));
        atomicAdd(&g_agg0[d0.x], __ldg(&in_feat[s0.x]));
        atomicAdd(&g_agg0[d0.y], __ldg(&in_feat[s0.y]));
        atomicAdd(&g_agg0[d0.z], __ldg(&in_feat[s0.z]));
        atomicAdd(&g_agg0[d0.w], __ldg(&in_feat[s0.w]));
        atomicAdd(&g_agg0[d1.x], __ldg(&in_feat[s1.x]));
        atomicAdd(&g_agg0[d1.y], __ldg(&in_feat[s1.y]));
        atomicAdd(&g_agg0[d1.z], __ldg(&in_feat[s1.z]));
        atomicAdd(&g_agg0[d1.w], __ldg(&in_feat[s1.w]));
    } else {
        for (int e = base; e < E; e++)
            atomicAdd(&g_agg0[dst[e]], __ldg(&in_feat[src[e]]));
    }
}

// ---------------- step 1: scan32 — dst == OUT_NODE ----------------
__device__ __forceinline__ void hit32(const int* __restrict__ src, int e) {
    int s = src[e];
    int p = atomicAdd(&g_e1n, 1);
    if (p < E1CAP) g_e1s[p] = s;
    unsigned m = 1u << (s & 31);
    unsigned old = atomicOr(&g_B2[s >> 5], m);
    if (!(old & m)) {
        int q = atomicAdd(&g_cnt2, 1);
        g_list2[q] = s;
        zero64(&g_agg2[(size_t)s * 64]);
    }
}
__global__ void k_scan32(const int* __restrict__ src, const int* __restrict__ dst, int E) {
    int t = blockIdx.x * blockDim.x + threadIdx.x;
    int base = t * 8;
    if (base + 7 < E) {
        int4 d0 = *(const int4*)(dst + base);
        int4 d1 = *(const int4*)(dst + base + 4);
        if (d0.x == OUT_NODE) hit32(src, base + 0);
        if (d0.y == OUT_NODE) hit32(src, base + 1);
        if (d0.z == OUT_NODE) hit32(src, base + 2);
        if (d0.w == OUT_NODE) hit32(src, base + 3);
        if (d1.x == OUT_NODE) hit32(src, base + 4);
        if (d1.y == OUT_NODE) hit32(src, base + 5);
        if (d1.z == OUT_NODE) hit32(src, base + 6);
        if (d1.w == OUT_NODE) hit32(src, base + 7);
    } else {
        for (int e = base; e < E; e++) if (dst[e] == OUT_NODE) hit32(src, e);
    }
}

// ---------------- step 2: scan21 — dst in B2 -> B1/list1/e2 ----------------
__device__ __forceinline__ void hit21(const int* __restrict__ src, int e, int d) {
    int s = src[e];
    int p = atomicAdd(&g_e2n, 1);
    if (p < E2CAP) { g_e2s[p] = s; g_e2d[p] = d; }
    unsigned m = 1u << (s & 31);
    unsigned old = atomicOr(&g_B1[s >> 5], m);
    if (!(old & m)) {
        int q = atomicAdd(&g_cnt1, 1);
        g_list1[q] = s;
        zero64(&g_agg1[(size_t)s * 64]);
    }
}
__global__ void k_scan21(const int* __restrict__ src, const int* __restrict__ dst, int E) {
    int t = blockIdx.x * blockDim.x + threadIdx.x;
    int base = t * 8;
    if (base + 7 < E) {
        int4 d0 = *(const int4*)(dst + base);
        int4 d1 = *(const int4*)(dst + base + 4);
        if (tb(g_B2, d0.x)) hit21(src, base + 0, d0.x);
        if (tb(g_B2, d0.y)) hit21(src, base + 1, d0.y);
        if (tb(g_B2, d0.z)) hit21(src, base + 2, d0.z);
        if (tb(g_B2, d0.w)) hit21(src, base + 3, d0.w);
        if (tb(g_B2, d1.x)) hit21(src, base + 4, d1.x);
        if (tb(g_B2, d1.y)) hit21(src, base + 5, d1.y);
        if (tb(g_B2, d1.z)) hit21(src, base + 6, d1.z);
        if (tb(g_B2, d1.w)) hit21(src, base + 7, d1.w);
    } else {
        for (int e = base; e < E; e++) { int d = dst[e]; if (tb(g_B2, d)) hit21(src, e, d); }
    }
}

// ---------------- step 3: scan10 + agg1 FUSED ----------------
// For each edge (s, d) with d in B1: agg1[d][j] += lrelu(agg0[s]*W0[j]+b0[j]).
__device__ __forceinline__ void hit10a(const int* __restrict__ src, int e, int d,
                                       const float* __restrict__ W0,
                                       const float* __restrict__ b0) {
    float a0 = g_agg0[src[e]];
    float* a = &g_agg1[(size_t)d * 64];
    #pragma unroll 8
    for (int j = 0; j < 64; j++)
        atomicAdd(&a[j], lrelu(fmaf(a0, __ldg(&W0[j]), __ldg(&b0[j]))));
}
__global__ void k_scan10agg1(const int* __restrict__ src, const int* __restrict__ dst, int E,
                             const float* __restrict__ W0, const float* __restrict__ b0) {
    int t = blockIdx.x * blockDim.x + threadIdx.x;
    int base = t * 8;
    if (base + 7 < E) {
        int4 d0 = *(const int4*)(dst + base);
        int4 d1 = *(const int4*)(dst + base + 4);
        if (tb(g_B1, d0.x)) hit10a(src, base + 0, d0.x, W0, b0);
        if (tb(g_B1, d0.y)) hit10a(src, base + 1, d0.y, W0, b0);
        if (tb(g_B1, d0.z)) hit10a(src, base + 2, d0.z, W0, b0);
        if (tb(g_B1, d0.w)) hit10a(src, base + 3, d0.w, W0, b0);
        if (tb(g_B1, d1.x)) hit10a(src, base + 4, d1.x, W0, b0);
        if (tb(g_B1, d1.y)) hit10a(src, base + 5, d1.y, W0, b0);
        if (tb(g_B1, d1.z)) hit10a(src, base + 6, d1.z, W0, b0);
        if (tb(g_B1, d1.w)) hit10a(src, base + 7, d1.w, W0, b0);
    } else {
        for (int e = base; e < E; e++) {
            int d = dst[e];
            if (tb(g_B1, d)) hit10a(src, e, d, W0, b0);
        }
    }
}

// ---------------- step 4: h1x2 — per node in list1 (warp/node) --------------
__global__ void k_h1x2(const float* __restrict__ W1, const float* __restrict__ b1,
                       const float* __restrict__ W2) {
    int n = g_cnt1;
    int lane = threadIdx.x & 31;
    int warp = (blockIdx.x * blockDim.x + threadIdx.x) >> 5;
    int nw = (gridDim.x * blockDim.x) >> 5;
    for (int i = warp; i < n; i += nw) {
        int v = g_list1[i];
        float a0 = g_agg1[(size_t)v * 64 + lane];
        float a1 = g_agg1[(size_t)v * 64 + lane + 32];
        float h0r = __ldg(&b1[lane]);
        float h1r = __ldg(&b1[lane + 32]);
        float h2r = __ldg(&b1[lane + 64]);
        float h3r = __ldg(&b1[lane + 96]);
        #pragma unroll
        for (int k = 0; k < 64; k++) {
            float ak = __shfl_sync(0xffffffffu, (k < 32) ? a0 : a1, k & 31);
            const float* wr = &W1[k * 128];
            h0r = fmaf(ak, __ldg(&wr[lane]),      h0r);
            h1r = fmaf(ak, __ldg(&wr[lane + 32]), h1r);
            h2r = fmaf(ak, __ldg(&wr[lane + 64]), h2r);
            h3r = fmaf(ak, __ldg(&wr[lane + 96]), h3r);
        }
        float h[4] = { lrelu(h0r), lrelu(h1r), lrelu(h2r), lrelu(h3r) };
        float x0 = 0.f, x1 = 0.f;
        #pragma unroll
        for (int k = 0; k < 128; k++) {
            float hk = __shfl_sync(0xffffffffu, h[k >> 5], k & 31);
            const float* wr = &W2[k * 64];
            x0 = fmaf(hk, __ldg(&wr[lane]),      x0);
            x1 = fmaf(hk, __ldg(&wr[lane + 32]), x1);
        }
        g_x2[(size_t)v * 64 + lane]      = x0;
        g_x2[(size_t)v * 64 + lane + 32] = x1;
    }
}

// ---------------- step 5: tail — agg2 + h2x3 + final + out + CLEANUP --------
__global__ void __launch_bounds__(1024, 1)
k_tail(const float* __restrict__ b2, const float* __restrict__ W3,
       const float* __restrict__ b3, float* __restrict__ out) {
    int lane = threadIdx.x & 31;
    int bw = threadIdx.x >> 5;

    int n2 = min(g_e2n, E2CAP);
    for (int i = bw; i < n2; i += 32) {
        int s = g_e2s[i], d = g_e2d[i];
        float* a = &g_agg2[(size_t)d * 64];
        atomicAdd(&a[lane],      __ldcg(&g_x2[(size_t)s * 64 + lane]));
        atomicAdd(&a[lane + 32], __ldcg(&g_x2[(size_t)s * 64 + lane + 32]));
    }
    __syncthreads();

    int n3 = g_cnt2;
    for (int i = bw; i < n3; i += 32) {
        int v = g_list2[i];
        float ya = lrelu(__ldcg(&g_agg2[(size_t)v * 64 + lane])      + __ldg(&b2[lane]));
        float yb = lrelu(__ldcg(&g_agg2[(size_t)v * 64 + lane + 32]) + __ldg(&b2[lane + 32]));
        float p = fmaf(ya, __ldg(&W3[lane]), yb * __ldg(&W3[lane + 32]));
        #pragma unroll
        for (int o = 16; o; o >>= 1) p += __shfl_down_sync(0xffffffffu, p, o);
        if (lane == 0) g_x3[v] = p;
    }
    __syncthreads();

    __shared__ float red[32];
    int n1 = min(g_e1n, E1CAP);
    float s = 0.f;
    for (int i = threadIdx.x; i < n1; i += 1024) s += __ldcg(&g_x3[g_e1s[i]]);
    #pragma unroll
    for (int o = 16; o; o >>= 1) s += __shfl_down_sync(0xffffffffu, s, o);
    if (lane == 0) red[bw] = s;
    __syncthreads();
    if (threadIdx.x < 32) {
        float t = red[lane];
        #pragma unroll
        for (int o = 16; o; o >>= 1) t += __shfl_down_sync(0xffffffffu, t, o);
        if (lane == 0) out[0] = lrelu(t + __ldg(&b3[0]));
    }
    __syncthreads();

    // ---- self-cleanup for the next graph replay ----
    int c2 = g_cnt2, c1 = g_cnt1;
    for (int i = threadIdx.x; i < c2; i += 1024) { int v = g_list2[i]; g_B2[v >> 5] = 0u; }
    for (int i = threadIdx.x; i < c1; i += 1024) { int v = g_list1[i]; g_B1[v >> 5] = 0u; }
    __syncthreads();
    if (threadIdx.x == 0) {
        g_cnt1 = 0; g_cnt2 = 0; g_e1n = 0; g_e2n = 0;
        __threadfence();
    }
}

// ---------------------------------------------------------------------------
extern "C" void kernel_launch(void* const* d_in, const int* in_sizes, int n_in,
                              void* d_out, int out_size) {
    const float* in_feat = (const float*)d_in[0];
    const int*   src     = (const int*)  d_in[1];
    const int*   dst     = (const int*)  d_in[2];
    const float* W0 = (const float*)d_in[3];
    const float* b0 = (const float*)d_in[4];
    const float* W1 = (const float*)d_in[5];
    const float* b1 = (const float*)d_in[6];
    const float* W2 = (const float*)d_in[7];
    const float* b2 = (const float*)d_in[8];
    const float* W3 = (const float*)d_in[9];
    const float* b3 = (const float*)d_in[10];
    float* out = (float*)d_out;

    int E = in_sizes[1];
    int T8 = (E + 7) / 8;                // one thread per 8 edges
    int sb = (T8 + 255) / 256;           // ~391 blocks — HALF the GPU,
                                         // so two such grids co-reside

    static cudaStream_t s2 = nullptr;
    static cudaEvent_t evF = nullptr, evJ = nullptr;
    if (!s2) {
        cudaStreamCreateWithFlags(&s2, cudaStreamNonBlocking);
        cudaEventCreateWithFlags(&evF, cudaEventDisableTiming);
        cudaEventCreateWithFlags(&evJ, cudaEventDisableTiming);
    }

    // fork: branch B (agg0 zero + all-edge layer-0 aggregation), half-GPU grid
    cudaEventRecord(evF, 0);
    cudaStreamWaitEvent(s2, evF, 0);
    k_zagg0<<<(MAXN + 255) / 256, 256, 0, s2>>>();
    k_agg0all<<<sb, 256, 0, s2>>>(src, dst, in_feat, E);
    cudaEventRecord(evJ, s2);

    // branch A: half-GPU scans overlap branch B
    k_scan32<<<sb, 256>>>(src, dst, E);
    k_scan21<<<sb, 256>>>(src, dst, E);
    cudaStreamWaitEvent(0, evJ, 0);              // agg0 ready before fusion
    k_scan10agg1<<<sb, 256>>>(src, dst, E, W0, b0);
    k_h1x2<<<128, 256>>>(W1, b1, W2);
    k_tail<<<1, 1024>>>(b2, W3, b3, out);
}

// round 16
// speedup vs baseline: 1.4289x; 1.4289x over previous
#include <cuda_runtime.h>

// ---------------------------------------------------------------------------
// DummyGCN4: 4-layer GCN, output = h3[node 1] only.
// R16 = R2 VERBATIM (best measured: 39.7us). Backward-slice + edge-list
// capture. Only 4 full edge scans (scan32, scan21, scan10, agg0), each
// vectorized int4 (4 edges/thread). Matching edges recorded during the
// backward scans so forward aggregations for layers 1/2/3 run on compact
// edge lists (~16..4k edges). Every deviation from this structure measured
// worse across rounds 3-15.
// ---------------------------------------------------------------------------

#define MAXN 50048
#define BMW  1568
#define OUT_NODE 1
#define E1CAP  16384      // edges with dst == OUT_NODE
#define E2CAP  65536      // edges with dst in B2
#define E1BCAP 262144     // edges with dst in B1

__device__ unsigned g_B0[BMW], g_B1[BMW], g_B2[BMW];
__device__ int   g_list0[MAXN], g_list1[MAXN], g_list2[MAXN];
__device__ int   g_cnt0, g_cnt1, g_cnt2;
__device__ int   g_e1s[E1CAP];               __device__ int g_e1n;
__device__ int   g_e2s[E2CAP],  g_e2d[E2CAP];  __device__ int g_e2n;
__device__ int   g_ebs[E1BCAP], g_ebd[E1BCAP]; __device__ int g_ebn;
__device__ float g_agg0[MAXN];
__device__ float g_h0[(size_t)MAXN * 64];
__device__ float g_agg1[(size_t)MAXN * 64];
__device__ float g_h1[(size_t)MAXN * 128];
__device__ float g_x2[(size_t)MAXN * 64];
__device__ float g_agg2[(size_t)MAXN * 64];
__device__ float g_x3[MAXN];

__device__ __forceinline__ float lrelu(float x) { return x >= 0.f ? x : 0.01f * x; }
__device__ __forceinline__ bool tb(const unsigned* b, int i) {
    return (b[i >> 5] >> (i & 31)) & 1u;
}
__device__ __forceinline__ void zero64(float* a) {
    float4 z = make_float4(0.f, 0.f, 0.f, 0.f);
    float4* a4 = (float4*)a;
    #pragma unroll
    for (int j = 0; j < 16; j++) a4[j] = z;
}

// ---------------- init ----------------
__global__ void k_clear() {
    int t = blockIdx.x * blockDim.x + threadIdx.x;
    if (t < BMW) { g_B0[t] = 0; g_B1[t] = 0; g_B2[t] = 0; }
    if (t == 0) { g_cnt0 = 0; g_cnt1 = 0; g_cnt2 = 0; g_e1n = 0; g_e2n = 0; g_ebn = 0; }
}

// ---------------- scan 1: dst == OUT_NODE ----------------
__device__ __forceinline__ void hit32(const int* __restrict__ src, int e) {
    int s = src[e];
    int p = atomicAdd(&g_e1n, 1);
    if (p < E1CAP) g_e1s[p] = s;
    unsigned m = 1u << (s & 31);
    unsigned old = atomicOr(&g_B2[s >> 5], m);
    if (!(old & m)) {
        int q = atomicAdd(&g_cnt2, 1);
        g_list2[q] = s;
        zero64(&g_agg2[(size_t)s * 64]);
    }
}
__global__ void k_scan32(const int* __restrict__ src, const int* __restrict__ dst, int E) {
    int t = blockIdx.x * blockDim.x + threadIdx.x;
    int base = t * 4;
    if (base + 3 < E) {
        int4 d4 = *(const int4*)(dst + base);
        if (d4.x == OUT_NODE) hit32(src, base + 0);
        if (d4.y == OUT_NODE) hit32(src, base + 1);
        if (d4.z == OUT_NODE) hit32(src, base + 2);
        if (d4.w == OUT_NODE) hit32(src, base + 3);
    } else {
        for (int e = base; e < E; e++) if (dst[e] == OUT_NODE) hit32(src, e);
    }
}

// ---------------- scan 2: dst in B2 ----------------
__device__ __forceinline__ void hit21(const int* __restrict__ src, int e, int d) {
    int s = src[e];
    int p = atomicAdd(&g_e2n, 1);
    if (p < E2CAP) { g_e2s[p] = s; g_e2d[p] = d; }
    unsigned m = 1u << (s & 31);
    unsigned old = atomicOr(&g_B1[s >> 5], m);
    if (!(old & m)) {
        int q = atomicAdd(&g_cnt1, 1);
        g_list1[q] = s;
        zero64(&g_agg1[(size_t)s * 64]);
    }
}
__global__ void k_scan21(const int* __restrict__ src, const int* __restrict__ dst, int E) {
    int t = blockIdx.x * blockDim.x + threadIdx.x;
    int base = t * 4;
    if (base + 3 < E) {
        int4 d4 = *(const int4*)(dst + base);
        if (tb(g_B2, d4.x)) hit21(src, base + 0, d4.x);
        if (tb(g_B2, d4.y)) hit21(src, base + 1, d4.y);
        if (tb(g_B2, d4.z)) hit21(src, base + 2, d4.z);
        if (tb(g_B2, d4.w)) hit21(src, base + 3, d4.w);
    } else {
        for (int e = base; e < E; e++) { int d = dst[e]; if (tb(g_B2, d)) hit21(src, e, d); }
    }
}

// ---------------- scan 3: dst in B1 ----------------
__device__ __forceinline__ void hit10(const int* __restrict__ src, int e, int d) {
    int s = src[e];
    int p = atomicAdd(&g_ebn, 1);
    if (p < E1BCAP) { g_ebs[p] = s; g_ebd[p] = d; }
    unsigned m = 1u << (s & 31);
    unsigned old = atomicOr(&g_B0[s >> 5], m);
    if (!(old & m)) {
        int q = atomicAdd(&g_cnt0, 1);
        g_list0[q] = s;
        g_agg0[s] = 0.f;
    }
}
__global__ void k_scan10(const int* __restrict__ src, const int* __restrict__ dst, int E) {
    int t = blockIdx.x * blockDim.x + threadIdx.x;
    int base = t * 4;
    if (base + 3 < E) {
        int4 d4 = *(const int4*)(dst + base);
        if (tb(g_B1, d4.x)) hit10(src, base + 0, d4.x);
        if (tb(g_B1, d4.y)) hit10(src, base + 1, d4.y);
        if (tb(g_B1, d4.z)) hit10(src, base + 2, d4.z);
        if (tb(g_B1, d4.w)) hit10(src, base + 3, d4.w);
    } else {
        for (int e = base; e < E; e++) { int d = dst[e]; if (tb(g_B1, d)) hit10(src, e, d); }
    }
}

// ---------------- scan 4: layer-0 aggregation (dst in B0) ----------------
__global__ void k_agg0(const int* __restrict__ src, const int* __restrict__ dst, int E,
                       const float* __restrict__ in_feat) {
    int t = blockIdx.x * blockDim.x + threadIdx.x;
    int base = t * 4;
    if (base + 3 < E) {
        int4 d4 = *(const int4*)(dst + base);
        if (tb(g_B0, d4.x)) atomicAdd(&g_agg0[d4.x], in_feat[src[base + 0]]);
        if (tb(g_B0, d4.y)) atomicAdd(&g_agg0[d4.y], in_feat[src[base + 1]]);
        if (tb(g_B0, d4.z)) atomicAdd(&g_agg0[d4.z], in_feat[src[base + 2]]);
        if (tb(g_B0, d4.w)) atomicAdd(&g_agg0[d4.w], in_feat[src[base + 3]]);
    } else {
        for (int e = base; e < E; e++) {
            int d = dst[e];
            if (tb(g_B0, d)) atomicAdd(&g_agg0[d], in_feat[src[e]]);
        }
    }
}

// h0[v] = lrelu(agg0[v] * W0 + b0), v in list0
__global__ void k_h0(const float* __restrict__ W0, const float* __restrict__ b0) {
    int j = threadIdx.x;            // 0..63
    int cnt = g_cnt0;
    for (int idx = blockIdx.x; idx < cnt; idx += gridDim.x) {
        int v = g_list0[idx];
        g_h0[(size_t)v * 64 + j] = lrelu(g_agg0[v] * W0[j] + b0[j]);
    }
}

// agg1[d][:] += h0[s][:] over compact edge list (warp per edge)
__global__ void k_agg1c() {
    int n = min(g_ebn, E1BCAP);
    int lane = threadIdx.x & 31;
    int warp = (blockIdx.x * blockDim.x + threadIdx.x) >> 5;
    int nw = (gridDim.x * blockDim.x) >> 5;
    for (int i = warp; i < n; i += nw) {
        int s = g_ebs[i], d = g_ebd[i];
        const float* h = &g_h0[(size_t)s * 64];
        float* a = &g_agg1[(size_t)d * 64];
        atomicAdd(&a[lane],      h[lane]);
        atomicAdd(&a[lane + 32], h[lane + 32]);
    }
}

// h1[v] = lrelu(agg1[v] @ W1 + b1), W1 [64,128]
__global__ void k_h1(const float* __restrict__ W1, const float* __restrict__ b1) {
    __shared__ float sa[64];
    int j = threadIdx.x;            // 0..127
    int cnt = g_cnt1;
    for (int idx = blockIdx.x; idx < cnt; idx += gridDim.x) {
        int v = g_list1[idx];
        if (j < 64) sa[j] = g_agg1[(size_t)v * 64 + j];
        __syncthreads();
        float acc = b1[j];
        #pragma unroll
        for (int k = 0; k < 64; k++) acc += sa[k] * W1[k * 128 + j];
        g_h1[(size_t)v * 128 + j] = lrelu(acc);
        __syncthreads();
    }
}

// x2[v] = h1[v] @ W2, W2 [128,64]
__global__ void k_x2(const float* __restrict__ W2) {
    __shared__ float sh[128];
    int j = threadIdx.x;            // 0..63
    int cnt = g_cnt1;
    for (int idx = blockIdx.x; idx < cnt; idx += gridDim.x) {
        int v = g_list1[idx];
        sh[j]      = g_h1[(size_t)v * 128 + j];
        sh[j + 64] = g_h1[(size_t)v * 128 + j + 64];
        __syncthreads();
        float acc = 0.f;
        #pragma unroll
        for (int k = 0; k < 128; k++) acc += sh[k] * W2[k * 64 + j];
        g_x2[(size_t)v * 64 + j] = acc;
        __syncthreads();
    }
}

// agg2[d][:] += x2[s][:] over compact edge list
__global__ void k_agg2c() {
    int n = min(g_e2n, E2CAP);
    int lane = threadIdx.x & 31;
    int warp = (blockIdx.x * blockDim.x + threadIdx.x) >> 5;
    int nw = (gridDim.x * blockDim.x) >> 5;
    for (int i = warp; i < n; i += nw) {
        int s = g_e2s[i], d = g_e2d[i];
        const float* x = &g_x2[(size_t)s * 64];
        float* a = &g_agg2[(size_t)d * 64];
        atomicAdd(&a[lane],      x[lane]);
        atomicAdd(&a[lane + 32], x[lane + 32]);
    }
}

// h2[v] = lrelu(agg2[v] + b2); x3[v] = h2[v] . W3
__global__ void k_h2x3(const float* __restrict__ b2, const float* __restrict__ W3) {
    __shared__ float s2[2];
    int j = threadIdx.x;            // 0..63
    int cnt = g_cnt2;
    for (int idx = blockIdx.x; idx < cnt; idx += gridDim.x) {
        int v = g_list2[idx];
        float y = lrelu(g_agg2[(size_t)v * 64 + j] + b2[j]);
        float p = y * W3[j];
        #pragma unroll
        for (int o = 16; o; o >>= 1) p += __shfl_down_sync(0xffffffffu, p, o);
        if ((j & 31) == 0) s2[j >> 5] = p;
        __syncthreads();
        if (j == 0) g_x3[v] = s2[0] + s2[1];
        __syncthreads();
    }
}

// out = lrelu(sum over node-1 in-edges of x3[src] + b3)
__global__ void k_out(const float* __restrict__ b3, float* __restrict__ out) {
    __shared__ float red[4];
    int n = min(g_e1n, E1CAP);
    float s = 0.f;
    for (int i = threadIdx.x; i < n; i += blockDim.x) s += g_x3[g_e1s[i]];
    #pragma unroll
    for (int o = 16; o; o >>= 1) s += __shfl_down_sync(0xffffffffu, s, o);
    if ((threadIdx.x & 31) == 0) red[threadIdx.x >> 5] = s;
    __syncthreads();
    if (threadIdx.x == 0) {
        float t = red[0] + red[1] + red[2] + red[3];
        out[0] = lrelu(t + b3[0]);
    }
}

// ---------------------------------------------------------------------------
extern "C" void kernel_launch(void* const* d_in, const int* in_sizes, int n_in,
                              void* d_out, int out_size) {
    const float* in_feat = (const float*)d_in[0];
    const int*   src     = (const int*)  d_in[1];
    const int*   dst     = (const int*)  d_in[2];
    const float* W0 = (const float*)d_in[3];
    const float* b0 = (const float*)d_in[4];
    const float* W1 = (const float*)d_in[5];
    const float* b1 = (const float*)d_in[6];
    const float* W2 = (const float*)d_in[7];
    const float* b2 = (const float*)d_in[8];
    const float* W3 = (const float*)d_in[9];
    const float* b3 = (const float*)d_in[10];
    float* out = (float*)d_out;

    int E = in_sizes[1];
    int T = (E + 3) / 4;                 // one thread per 4 edges
    int sb = (T + 255) / 256;

    k_clear<<<(BMW + 255) / 256, 256>>>();

    k_scan32<<<sb, 256>>>(src, dst, E);
    k_scan21<<<sb, 256>>>(src, dst, E);
    k_scan10<<<sb, 256>>>(src, dst, E);

    k_agg0<<<sb, 256>>>(src, dst, E, in_feat);
    k_h0<<<1024, 64>>>(W0, b0);
    k_agg1c<<<512, 256>>>();
    k_h1<<<512, 128>>>(W1, b1);
    k_x2<<<512, 64>>>(W2);
    k_agg2c<<<64, 256>>>();
    k_h2x3<<<32, 64>>>(b2, W3);
    k_out<<<1, 128>>>(b3, out);
}